// round 6
// baseline (speedup 1.0000x reference)
#include <cuda_runtime.h>

// Shape: a, b, h : (B=2, S=2048, D=1024, N=16) fp32, row-major.
// h[t] = a[t]*h[t-1] + b[t] along S. B*D*N = 32768 independent channels,
// contiguous at fixed t; scan stride = D*N = 16384 floats.
//
// R5: identical U=8/distance-4 register pipeline, but re-tiled to
// block=64 / grid=512 so all 148 SMs are active (R4 used 128 blocks ->
// 20 idle SMs). Binding resource is the ~248-entry per-SM L1tex wavefront
// queue; every SM now holds >= 6 warps x 55 slots > 248 -> all 148 queues
// pinned -> +15.6% chip-wide in-flight bytes.

static constexpr int S_LEN   = 2048;
static constexpr int STRIDE  = 1024 * 16;       // D*N floats between timesteps
static constexpr int CHANNELS = 2 * STRIDE;     // 32768
static constexpr int U       = 8;               // timesteps per group
static constexpr int N_GROUPS = S_LEN / U;      // 256
static constexpr int N_SUPER  = N_GROUPS / 8;   // 32 super-iterations (8 groups each)
static constexpr int BLOCK   = 64;

// Load local group G (relative to current ap/bp) into buffers A/B.
#define PREF(A, B, G)                                            \
    _Pragma("unroll")                                            \
    for (int u = 0; u < U; u++) {                                \
        A[u] = __ldcs(ap + ((G) * U + u) * STRIDE);              \
        B[u] = __ldcs(bp + ((G) * U + u) * STRIDE);              \
    }

// Consume buffers A/B as local group G: serial FMA chain + streaming stores.
#define CONS(A, B, G)                                            \
    _Pragma("unroll")                                            \
    for (int u = 0; u < U; u++) {                                \
        h = fmaf(A[u], h, B[u]);                                 \
        __stcs(op + ((G) * U + u) * STRIDE, h);                  \
    }

__global__ __launch_bounds__(BLOCK, 4)
void ParallelScan_37374805409922_kernel(const float* __restrict__ a,
                                        const float* __restrict__ b,
                                        float* __restrict__ out) {
    const int idx   = blockIdx.x * BLOCK + threadIdx.x;        // 0..32767
    const int batch = idx >> 14;                               // / 16384
    const int col   = idx & (STRIDE - 1);
    const size_t base = (size_t)batch * S_LEN * STRIDE + col;

    const float* __restrict__ ap = a + base;
    const float* __restrict__ bp = b + base;
    float* __restrict__ op = out + base;

    float a0[U], b0[U], a1[U], b1[U], a2[U], b2[U], a3[U], b3[U];
    float a4[U], b4[U], a5[U], b5[U], a6[U], b6[U], a7[U], b7[U];
    float h = 0.0f;

    // Prologue: 4 groups in flight before any consumption.
    PREF(a0, b0, 0)
    PREF(a1, b1, 1)
    PREF(a2, b2, 2)
    PREF(a3, b3, 3)

    #pragma unroll 1
    for (int s = 0; s < N_SUPER; s++) {
        // Steady state: issue one group of loads, consume one group — always
        // 4 groups of loads ahead of the consume point.
        PREF(a4, b4, 4)  CONS(a0, b0, 0)
        PREF(a5, b5, 5)  CONS(a1, b1, 1)
        PREF(a6, b6, 6)  CONS(a2, b2, 2)
        PREF(a7, b7, 7)  CONS(a3, b3, 3)

        if (s + 1 < N_SUPER) {
            PREF(a0, b0, 8)   CONS(a4, b4, 4)
            PREF(a1, b1, 9)   CONS(a5, b5, 5)
            PREF(a2, b2, 10)  CONS(a6, b6, 6)
            PREF(a3, b3, 11)  CONS(a7, b7, 7)
        } else {
            CONS(a4, b4, 4)
            CONS(a5, b5, 5)
            CONS(a6, b6, 6)
            CONS(a7, b7, 7)
        }

        ap += 8 * U * STRIDE;
        bp += 8 * U * STRIDE;
        op += 8 * U * STRIDE;
    }
}

extern "C" void kernel_launch(void* const* d_in, const int* in_sizes, int n_in,
                              void* d_out, int out_size) {
    const float* a = (const float*)d_in[0];
    const float* b = (const float*)d_in[1];
    float* out = (float*)d_out;
    (void)in_sizes; (void)n_in; (void)out_size;

    ParallelScan_37374805409922_kernel<<<CHANNELS / BLOCK, BLOCK>>>(a, b, out);
}

// round 7
// speedup vs baseline: 1.0409x; 1.0409x over previous
#include <cuda_runtime.h>

// Shape: a, b, h : (B=2, S=2048, D=1024, N=16) fp32, row-major.
// h[t] = a[t]*h[t-1] + b[t] along S. B*D*N = 32768 independent channels,
// contiguous at fixed t; scan stride = D*N = 16384 floats.
//
// R6: R5's U=8/distance-4 register pipeline + prefetch.global.L2 issued
// 8 groups (64 timesteps) ahead of the demand loads. Demand LDGs become L2
// hits (~240cyc); the DRAM side is driven by the L2-prefetch path, which
// bypasses the SM-side demand-miss tracking that R3-R5 showed is saturated
// (DRAM% invariant at ~68% vs per-warp depth and SM coverage).

static constexpr int S_LEN   = 2048;
static constexpr int STRIDE  = 1024 * 16;       // D*N floats between timesteps
static constexpr int CHANNELS = 2 * STRIDE;     // 32768
static constexpr int U       = 8;               // timesteps per group
static constexpr int N_GROUPS = S_LEN / U;      // 256
static constexpr int N_SUPER  = N_GROUPS / 8;   // 32 super-iterations (8 groups each)
static constexpr int BLOCK   = 64;
static constexpr int PF_G    = 12;              // prefetch lead (groups) vs consume

// Demand-load local group G (relative to current ap/bp) into buffers A/B.
#define PREF(A, B, G)                                            \
    _Pragma("unroll")                                            \
    for (int u = 0; u < U; u++) {                                \
        A[u] = __ldcs(ap + ((G) * U + u) * STRIDE);              \
        B[u] = __ldcs(bp + ((G) * U + u) * STRIDE);              \
    }

// Consume buffers A/B as local group G: serial FMA chain + streaming stores.
#define CONS(A, B, G)                                            \
    _Pragma("unroll")                                            \
    for (int u = 0; u < U; u++) {                                \
        h = fmaf(A[u], h, B[u]);                                 \
        __stcs(op + ((G) * U + u) * STRIDE, h);                  \
    }

// L2-prefetch local group G (uniform-predicated range guard; pfa/pfb are
// pre-advanced by PF_G groups so imm offsets stay within +-8MB).
#define PFL2(G)                                                  \
    if ((s * 8 + (G)) < N_GROUPS) {                              \
        _Pragma("unroll")                                        \
        for (int u = 0; u < U; u++) {                            \
            asm volatile("prefetch.global.L2 [%0];" ::           \
                "l"(pfa + (((G) - PF_G) * U + u) * STRIDE));     \
            asm volatile("prefetch.global.L2 [%0];" ::           \
                "l"(pfb + (((G) - PF_G) * U + u) * STRIDE));     \
        }                                                        \
    }

__global__ __launch_bounds__(BLOCK, 4)
void ParallelScan_37374805409922_kernel(const float* __restrict__ a,
                                        const float* __restrict__ b,
                                        float* __restrict__ out) {
    const int idx   = blockIdx.x * BLOCK + threadIdx.x;        // 0..32767
    const int batch = idx >> 14;                               // / 16384
    const int col   = idx & (STRIDE - 1);
    const size_t base = (size_t)batch * S_LEN * STRIDE + col;

    const float* __restrict__ ap = a + base;
    const float* __restrict__ bp = b + base;
    float* __restrict__ op = out + base;
    const float* pfa = ap + PF_G * U * STRIDE;
    const float* pfb = bp + PF_G * U * STRIDE;

    float a0[U], b0[U], a1[U], b1[U], a2[U], b2[U], a3[U], b3[U];
    float a4[U], b4[U], a5[U], b5[U], a6[U], b6[U], a7[U], b7[U];
    float h = 0.0f;

    // Prologue: 4 groups demand-loaded before any consumption.
    PREF(a0, b0, 0)
    PREF(a1, b1, 1)
    PREF(a2, b2, 2)
    PREF(a3, b3, 3)

    #pragma unroll 1
    for (int s = 0; s < N_SUPER; s++) {
        // Each slot: L2-prefetch 12 groups ahead, demand-load 4 ahead,
        // consume current.
        PFL2(12)  PREF(a4, b4, 4)  CONS(a0, b0, 0)
        PFL2(13)  PREF(a5, b5, 5)  CONS(a1, b1, 1)
        PFL2(14)  PREF(a6, b6, 6)  CONS(a2, b2, 2)
        PFL2(15)  PREF(a7, b7, 7)  CONS(a3, b3, 3)

        if (s + 1 < N_SUPER) {
            PFL2(16)  PREF(a0, b0, 8)   CONS(a4, b4, 4)
            PFL2(17)  PREF(a1, b1, 9)   CONS(a5, b5, 5)
            PFL2(18)  PREF(a2, b2, 10)  CONS(a6, b6, 6)
            PFL2(19)  PREF(a3, b3, 11)  CONS(a7, b7, 7)
        } else {
            CONS(a4, b4, 4)
            CONS(a5, b5, 5)
            CONS(a6, b6, 6)
            CONS(a7, b7, 7)
        }

        ap  += 8 * U * STRIDE;
        bp  += 8 * U * STRIDE;
        op  += 8 * U * STRIDE;
        pfa += 8 * U * STRIDE;
        pfb += 8 * U * STRIDE;
    }
}

extern "C" void kernel_launch(void* const* d_in, const int* in_sizes, int n_in,
                              void* d_out, int out_size) {
    const float* a = (const float*)d_in[0];
    const float* b = (const float*)d_in[1];
    float* out = (float*)d_out;
    (void)in_sizes; (void)n_in; (void)out_size;

    ParallelScan_37374805409922_kernel<<<CHANNELS / BLOCK, BLOCK>>>(a, b, out);
}

// round 8
// speedup vs baseline: 1.0490x; 1.0077x over previous
#include <cuda_runtime.h>

// Shape: a, b, h : (B=2, S=2048, D=1024, N=16) fp32, row-major.
// h[t] = a[t]*h[t-1] + b[t] along S. B*D*N = 32768 independent channels,
// contiguous at fixed t; scan stride = D*N = 16384 floats.
//
// R7: replace per-line prefetch.global.L2 hints (droppable, LSU queue) with
// cp.async.bulk.prefetch.L2.global through the TMA-class bulk engine.
// block=256 -> each block owns a 1 KB contiguous slice per timestep per
// tensor; one elected thread bulk-prefetches 1 KB x 2 tensors per timestep,
// 8 groups (64 timesteps, ~4 us) ahead of the demand loads. Demand U=8 /
// distance-4 register pipeline unchanged; demand LDGs hit L2.

static constexpr int S_LEN   = 2048;
static constexpr int STRIDE  = 1024 * 16;       // D*N floats between timesteps
static constexpr int CHANNELS = 2 * STRIDE;     // 32768
static constexpr int U       = 8;               // timesteps per group
static constexpr int N_GROUPS = S_LEN / U;      // 256
static constexpr int N_SUPER  = N_GROUPS / 8;   // 32 super-iterations
static constexpr int BLOCK   = 256;
static constexpr int PF_G    = 12;              // prefetch slot index within window
static constexpr int SLICE_B = BLOCK * 4;       // 1 KB contiguous per timestep

// Demand-load local group G (relative to current ap/bp) into buffers A/B.
#define PREF(A, B, G)                                            \
    _Pragma("unroll")                                            \
    for (int u = 0; u < U; u++) {                                \
        A[u] = __ldcs(ap + ((G) * U + u) * STRIDE);              \
        B[u] = __ldcs(bp + ((G) * U + u) * STRIDE);              \
    }

// Consume buffers A/B as local group G: serial FMA chain + streaming stores.
#define CONS(A, B, G)                                            \
    _Pragma("unroll")                                            \
    for (int u = 0; u < U; u++) {                                \
        h = fmaf(A[u], h, B[u]);                                 \
        __stcs(op + ((G) * U + u) * STRIDE, h);                  \
    }

// Bulk L2-prefetch local group G: one elected thread per block prefetches the
// block's 1 KB slice of a and b for each of the group's 8 timesteps.
#define PFBULK(G)                                                           \
    if (lead && (s * 8 + (G)) < N_GROUPS) {                                 \
        _Pragma("unroll")                                                   \
        for (int u = 0; u < U; u++) {                                       \
            asm volatile("cp.async.bulk.prefetch.L2.global [%0], %1;" ::    \
                "l"(pfa_g + (unsigned long long)(((G) - PF_G) * U + u) *    \
                            (STRIDE * 4ull)), "r"(SLICE_B));                \
            asm volatile("cp.async.bulk.prefetch.L2.global [%0], %1;" ::    \
                "l"(pfb_g + (unsigned long long)(((G) - PF_G) * U + u) *    \
                            (STRIDE * 4ull)), "r"(SLICE_B));                \
        }                                                                   \
    }

__global__ __launch_bounds__(BLOCK, 1)
void ParallelScan_37374805409922_kernel(const float* __restrict__ a,
                                        const float* __restrict__ b,
                                        float* __restrict__ out) {
    const int idx   = blockIdx.x * BLOCK + threadIdx.x;        // 0..32767
    const int batch = idx >> 14;                               // / 16384
    const int col   = idx & (STRIDE - 1);
    const size_t base = (size_t)batch * S_LEN * STRIDE + col;

    const float* __restrict__ ap = a + base;
    const float* __restrict__ bp = b + base;
    float* __restrict__ op = out + base;

    // Block-slice base (channel of lane 0 of this block) for bulk prefetch,
    // pre-advanced by PF_G groups; global address space.
    const bool lead = (threadIdx.x == 0);
    const int blk_col = (blockIdx.x * BLOCK) & (STRIDE - 1);
    const size_t blk_base = (size_t)((blockIdx.x * BLOCK) >> 14) * S_LEN * STRIDE
                          + blk_col + (size_t)PF_G * U * STRIDE;
    unsigned long long pfa_g = (unsigned long long)__cvta_generic_to_global(a + blk_base);
    unsigned long long pfb_g = (unsigned long long)__cvta_generic_to_global(b + blk_base);

    float a0[U], b0[U], a1[U], b1[U], a2[U], b2[U], a3[U], b3[U];
    float a4[U], b4[U], a5[U], b5[U], a6[U], b6[U], a7[U], b7[U];
    float h = 0.0f;

    // Prologue: bulk-prefetch the first lead window, then demand-load 4 groups.
    if (lead) {
        #pragma unroll 1
        for (int t = 4 * U; t < PF_G * U; t++) {
            asm volatile("cp.async.bulk.prefetch.L2.global [%0], %1;" ::
                "l"(pfa_g + (unsigned long long)(t - PF_G * U) * (STRIDE * 4ull)),
                "r"(SLICE_B));
            asm volatile("cp.async.bulk.prefetch.L2.global [%0], %1;" ::
                "l"(pfb_g + (unsigned long long)(t - PF_G * U) * (STRIDE * 4ull)),
                "r"(SLICE_B));
        }
    }
    PREF(a0, b0, 0)
    PREF(a1, b1, 1)
    PREF(a2, b2, 2)
    PREF(a3, b3, 3)

    #pragma unroll 1
    for (int s = 0; s < N_SUPER; s++) {
        // Each slot: bulk-prefetch 12 groups ahead, demand-load 4 ahead,
        // consume current.
        PFBULK(12)  PREF(a4, b4, 4)  CONS(a0, b0, 0)
        PFBULK(13)  PREF(a5, b5, 5)  CONS(a1, b1, 1)
        PFBULK(14)  PREF(a6, b6, 6)  CONS(a2, b2, 2)
        PFBULK(15)  PREF(a7, b7, 7)  CONS(a3, b3, 3)

        if (s + 1 < N_SUPER) {
            PFBULK(16)  PREF(a0, b0, 8)   CONS(a4, b4, 4)
            PFBULK(17)  PREF(a1, b1, 9)   CONS(a5, b5, 5)
            PFBULK(18)  PREF(a2, b2, 10)  CONS(a6, b6, 6)
            PFBULK(19)  PREF(a3, b3, 11)  CONS(a7, b7, 7)
        } else {
            CONS(a4, b4, 4)
            CONS(a5, b5, 5)
            CONS(a6, b6, 6)
            CONS(a7, b7, 7)
        }

        ap    += 8 * U * STRIDE;
        bp    += 8 * U * STRIDE;
        op    += 8 * U * STRIDE;
        pfa_g += 8ull * U * STRIDE * 4ull;
        pfb_g += 8ull * U * STRIDE * 4ull;
    }
}

extern "C" void kernel_launch(void* const* d_in, const int* in_sizes, int n_in,
                              void* d_out, int out_size) {
    const float* a = (const float*)d_in[0];
    const float* b = (const float*)d_in[1];
    float* out = (float*)d_out;
    (void)in_sizes; (void)n_in; (void)out_size;

    ParallelScan_37374805409922_kernel<<<CHANNELS / BLOCK, BLOCK>>>(a, b, out);
}